// round 6
// baseline (speedup 1.0000x reference)
#include <cuda_runtime.h>

#define HID 512
#define H3  256
#define TB  48          // batch rows per CTA
#define NTHREADS 512
#define RPT 3           // rows per thread = TB / (NTHREADS/32)

__global__ void __launch_bounds__(NTHREADS, 1)
node_rk4_kernel(const float* __restrict__ y0,
                const float* __restrict__ tp,
                const float* __restrict__ W1, const float* __restrict__ b1,
                const float* __restrict__ W2, const float* __restrict__ b2,
                const float* __restrict__ W3, const float* __restrict__ b3,
                const float* __restrict__ W4, const float* __restrict__ b4,
                float* __restrict__ out, int B, int T)
{
    extern __shared__ float sm[];
    float* bufA   = sm;                    // TB*HID
    float* bufB   = sm + TB * HID;         // TB*HID
    float* ycur   = sm + 2 * TB * HID;     // TB*2
    float* ystage = ycur + TB * 2;         // TB*2
    float* ysum   = ystage + TB * 2;       // TB*2

    const int tid  = threadIdx.x;
    const int lane = tid & 31;
    const int r0   = (tid >> 5) * RPT;     // first of my 3 rows
    const int base = blockIdx.x * TB;

    // ---- init state + write t=0 snapshot ----
    if (tid < TB * 2) {
        int r = tid >> 1, c = tid & 1;
        long g = (long)base + r;
        float v = (g < B) ? y0[g * 2 + c] : 0.0f;
        ycur[tid] = v;
        if (g < B) out[g * 2 + c] = v;
    }
    __syncthreads();

    for (int s = 0; s < T - 1; ++s) {
        const float dt = tp[s + 1] - tp[s];

        #pragma unroll 1
        for (int stage = 0; stage < 4; ++stage) {
            const float* yin = (stage == 0) ? ycur : ystage;

            // ================= layer 1: (2 -> 512), out -> bufA =================
            {
                const int c0 = lane * 16;
                float w0c[16], w1c[16], bb[16];
                #pragma unroll
                for (int c = 0; c < 16; ++c) {
                    w0c[c] = W1[c0 + c];
                    w1c[c] = W1[HID + c0 + c];
                    bb[c]  = b1[c0 + c];
                }
                #pragma unroll
                for (int i = 0; i < RPT; ++i) {
                    const int r = r0 + i;
                    const float a0 = yin[r * 2 + 0];
                    const float a1 = yin[r * 2 + 1];
                    #pragma unroll
                    for (int c = 0; c < 16; ++c) {
                        float acc = fmaf(a0, w0c[c], fmaf(a1, w1c[c], bb[c]));
                        bufA[r * HID + c0 + c] = tanhf(acc);
                    }
                }
            }
            __syncthreads();

            // ================= layer 2: (512 -> 512), bufA -> bufB ==============
            {
                const int c0 = lane * 16;
                float acc[RPT][16];
                #pragma unroll
                for (int i = 0; i < RPT; ++i)
                    #pragma unroll
                    for (int c = 0; c < 16; ++c) acc[i][c] = 0.0f;

                const float* A0 = bufA + r0 * HID;
                #pragma unroll 4
                for (int k = 0; k < HID; ++k) {
                    const float4 w0 = *(const float4*)(W2 + (size_t)k * HID + c0);
                    const float4 w1 = *(const float4*)(W2 + (size_t)k * HID + c0 + 4);
                    const float4 w2 = *(const float4*)(W2 + (size_t)k * HID + c0 + 8);
                    const float4 w3 = *(const float4*)(W2 + (size_t)k * HID + c0 + 12);
                    float a[RPT];
                    #pragma unroll
                    for (int i = 0; i < RPT; ++i) a[i] = A0[i * HID + k];
                    #pragma unroll
                    for (int i = 0; i < RPT; ++i) {
                        acc[i][0]  = fmaf(a[i], w0.x, acc[i][0]);
                        acc[i][1]  = fmaf(a[i], w0.y, acc[i][1]);
                        acc[i][2]  = fmaf(a[i], w0.z, acc[i][2]);
                        acc[i][3]  = fmaf(a[i], w0.w, acc[i][3]);
                        acc[i][4]  = fmaf(a[i], w1.x, acc[i][4]);
                        acc[i][5]  = fmaf(a[i], w1.y, acc[i][5]);
                        acc[i][6]  = fmaf(a[i], w1.z, acc[i][6]);
                        acc[i][7]  = fmaf(a[i], w1.w, acc[i][7]);
                        acc[i][8]  = fmaf(a[i], w2.x, acc[i][8]);
                        acc[i][9]  = fmaf(a[i], w2.y, acc[i][9]);
                        acc[i][10] = fmaf(a[i], w2.z, acc[i][10]);
                        acc[i][11] = fmaf(a[i], w2.w, acc[i][11]);
                        acc[i][12] = fmaf(a[i], w3.x, acc[i][12]);
                        acc[i][13] = fmaf(a[i], w3.y, acc[i][13]);
                        acc[i][14] = fmaf(a[i], w3.z, acc[i][14]);
                        acc[i][15] = fmaf(a[i], w3.w, acc[i][15]);
                    }
                }
                #pragma unroll
                for (int i = 0; i < RPT; ++i) {
                    const int r = r0 + i;
                    #pragma unroll
                    for (int c = 0; c < 16; ++c)
                        bufB[r * HID + c0 + c] = tanhf(acc[i][c] + b2[c0 + c]);
                }
            }
            __syncthreads();

            // ================= layer 3: (512 -> 256), bufB -> bufA ==============
            {
                const int c0 = lane * 8;
                float acc[RPT][8];
                #pragma unroll
                for (int i = 0; i < RPT; ++i)
                    #pragma unroll
                    for (int c = 0; c < 8; ++c) acc[i][c] = 0.0f;

                const float* A0 = bufB + r0 * HID;
                #pragma unroll 4
                for (int k = 0; k < HID; ++k) {
                    const float4 w0 = *(const float4*)(W3 + (size_t)k * H3 + c0);
                    const float4 w1 = *(const float4*)(W3 + (size_t)k * H3 + c0 + 4);
                    float a[RPT];
                    #pragma unroll
                    for (int i = 0; i < RPT; ++i) a[i] = A0[i * HID + k];
                    #pragma unroll
                    for (int i = 0; i < RPT; ++i) {
                        acc[i][0] = fmaf(a[i], w0.x, acc[i][0]);
                        acc[i][1] = fmaf(a[i], w0.y, acc[i][1]);
                        acc[i][2] = fmaf(a[i], w0.z, acc[i][2]);
                        acc[i][3] = fmaf(a[i], w0.w, acc[i][3]);
                        acc[i][4] = fmaf(a[i], w1.x, acc[i][4]);
                        acc[i][5] = fmaf(a[i], w1.y, acc[i][5]);
                        acc[i][6] = fmaf(a[i], w1.z, acc[i][6]);
                        acc[i][7] = fmaf(a[i], w1.w, acc[i][7]);
                    }
                }
                #pragma unroll
                for (int i = 0; i < RPT; ++i) {
                    const int r = r0 + i;
                    #pragma unroll
                    for (int c = 0; c < 8; ++c)
                        bufA[r * H3 + c0 + c] = tanhf(acc[i][c] + b3[c0 + c]);
                }
            }
            __syncthreads();

            // ===== layer 4 (256 -> 2) + RK4 stage update (96 threads) ==========
            if (tid < TB * 2) {
                const int r = tid >> 1, comp = tid & 1;
                const float* h = bufA + r * H3;
                float acc = b4[comp];
                #pragma unroll 8
                for (int k = 0; k < H3; ++k)
                    acc = fmaf(h[k], W4[k * 2 + comp], acc);

                const float f = acc;
                if (stage == 0) {
                    ysum[tid]   = f;
                    ystage[tid] = fmaf(0.5f * dt, f, ycur[tid]);
                } else if (stage == 1) {
                    ysum[tid]  += 2.0f * f;
                    ystage[tid] = fmaf(0.5f * dt, f, ycur[tid]);
                } else if (stage == 2) {
                    ysum[tid]  += 2.0f * f;
                    ystage[tid] = fmaf(dt, f, ycur[tid]);
                } else {
                    const float yn = fmaf(dt * (1.0f / 6.0f), ysum[tid] + f, ycur[tid]);
                    ycur[tid] = yn;
                    long g = (long)base + r;
                    if (g < B)
                        out[(size_t)(s + 1) * B * 2 + g * 2 + comp] = yn;
                }
            }
            __syncthreads();
        }
    }
}

extern "C" void kernel_launch(void* const* d_in, const int* in_sizes, int n_in,
                              void* d_out, int out_size) {
    const float* y0 = (const float*)d_in[0];
    const float* tp = (const float*)d_in[1];
    const float* W1 = (const float*)d_in[2];
    const float* b1 = (const float*)d_in[3];
    const float* W2 = (const float*)d_in[4];
    const float* b2 = (const float*)d_in[5];
    const float* W3 = (const float*)d_in[6];
    const float* b3 = (const float*)d_in[7];
    const float* W4 = (const float*)d_in[8];
    const float* b4 = (const float*)d_in[9];
    float* out = (float*)d_out;

    const int B = in_sizes[0] / 2;   // 65536
    const int T = in_sizes[1];       // 100

    const size_t smem = (size_t)(2 * TB * HID + 3 * TB * 2) * sizeof(float);
    cudaFuncSetAttribute(node_rk4_kernel,
                         cudaFuncAttributeMaxDynamicSharedMemorySize, (int)smem);

    const int grid = (B + TB - 1) / TB;
    node_rk4_kernel<<<grid, NTHREADS, smem>>>(y0, tp, W1, b1, W2, b2,
                                              W3, b3, W4, b4, out, B, T);
}